// round 5
// baseline (speedup 1.0000x reference)
#include <cuda_runtime.h>
#include <math.h>

#define LSEQ   256
#define NN     608
#define DM     32
#define DI     64
#define DSTATE 16
#define NB     32
#define VV     19
#define NG     4
#define GS     4

// ---------------- scratch (__device__ globals; no runtime allocs) ------------
__device__ float g_deg[NN];
__device__ float g_M[NN * VV];                  // row v (=dst): M[v][src_local]
__device__ float g_u [LSEQ * NN * DI];          // x (u_t): [t][node][64]
__device__ float g_dt[LSEQ * NN * DI];          // softplus(dt)
__device__ float g_sz[LSEQ * NN * DI];          // silu(z)
__device__ float g_uB[LSEQ * NN * DI];          // gcn_vec(u_t; gB_w, gB_b)
__device__ float g_Bm[LSEQ * NN * DSTATE];
__device__ float g_Cm[LSEQ * NN * DSTATE];
__device__ float g_yp[LSEQ * NN * DI * NG];     // partial y, interleaved by group

// ---------------- degree (deterministic fixed-order reduction) + zero M ------
__global__ void k_deg(const int* __restrict__ ei, const float* __restrict__ ew, int E) {
    int v = blockIdx.x;
    if (threadIdx.x < VV) g_M[v * VV + threadIdx.x] = 0.f;
    float acc = 0.f;
    for (int e = threadIdx.x; e < E; e += 256)
        if (ei[E + e] == v) acc += ew[e];
    __shared__ float red[256];
    red[threadIdx.x] = acc;
    __syncthreads();
    for (int s = 128; s > 0; s >>= 1) {
        if (threadIdx.x < s) red[threadIdx.x] += red[threadIdx.x + s];
        __syncthreads();
    }
    if (threadIdx.x == 0) g_deg[v] = red[0] + 1.0f;   // self loop weight 1
}

// ---------------- dense per-batch GCN norm matrix ---------------------------
__global__ void k_buildM(const int* __restrict__ ei, const float* __restrict__ ew, int E) {
    int i = blockIdx.x * 256 + threadIdx.x;
    if (i < E) {
        int s = ei[i], d = ei[E + i];
        int b = d / VV;
        int sl = s - b * VV;
        float ds = rsqrtf(fmaxf(g_deg[s], 1e-12f));
        float dd = rsqrtf(fmaxf(g_deg[d], 1e-12f));
        g_M[d * VV + sl] = ew[i] * ds * dd;
    } else if (i < E + NN) {
        int v = i - E;
        int vl = v % VV;
        float di = rsqrtf(fmaxf(g_deg[v], 1e-12f));
        g_M[v * VV + vl] = di * di;
    }
}

// ---------------- projections: u, silu(z), dt, B, C -------------------------
__global__ void __launch_bounds__(128) k_proj(
    const float* __restrict__ x_in, const float* __restrict__ ipw,
    const float* __restrict__ xpw,  const float* __restrict__ dtw,
    const float* __restrict__ dtb) {
    int v  = blockIdx.x;
    int t0 = blockIdx.y * 16;
    int e  = threadIdx.x;                       // 0..127
    __shared__ __align__(16) float sxin[16 * DM];
    __shared__ __align__(16) float sx  [16 * DI];
    __shared__ float sdtr[16 * 2];

    for (int idx = e; idx < 16 * DM; idx += 128)
        sxin[idx] = x_in[(v * LSEQ + t0) * DM + idx];

    float4 w[8];
    const float4* ipw4 = (const float4*)ipw;
#pragma unroll
    for (int j = 0; j < 8; j++) w[j] = ipw4[e * 8 + j];
    __syncthreads();

#pragma unroll 4
    for (int p = 0; p < 16; p++) {
        const float4* xx = (const float4*)(sxin + p * DM);
        float acc = 0.f;
#pragma unroll
        for (int j = 0; j < 8; j++) {
            float4 a = xx[j];
            acc += w[j].x * a.x + w[j].y * a.y + w[j].z * a.z + w[j].w * a.w;
        }
        int base = ((t0 + p) * NN + v) * DI;
        if (e < DI) { sx[p * DI + e] = acc; g_u[base + e] = acc; }
        else        { g_sz[base + (e - DI)] = acc / (1.f + __expf(-acc)); }
    }
    __syncthreads();

    for (int task = e; task < 16 * 34; task += 128) {
        int p = task / 34, j = task - p * 34;
        const float4* xr = (const float4*)(sx + p * DI);
        const float4* wr = (const float4*)(xpw + j * DI);
        float acc = 0.f;
#pragma unroll
        for (int q = 0; q < 16; q++) {
            float4 a = xr[q], b = wr[q];
            acc += a.x * b.x + a.y * b.y + a.z * b.z + a.w * b.w;
        }
        int t = t0 + p;
        if (j < 2)       sdtr[p * 2 + j] = acc;
        else if (j < 18) g_Bm[(t * NN + v) * DSTATE + (j - 2)]  = acc;
        else             g_Cm[(t * NN + v) * DSTATE + (j - 18)] = acc;
    }
    __syncthreads();

    for (int task = e; task < 16 * 64; task += 128) {
        int p = task >> 6, d = task & 63;
        float xv = dtw[d * 2] * sdtr[p * 2] + dtw[d * 2 + 1] * sdtr[p * 2 + 1] + dtb[d];
        g_dt[((t0 + p) * NN + v) * DI + d] = (xv > 20.f) ? xv : log1pf(expf(xv));
    }
}

// ---------------- uB = M @ (u @ gB_w^T) + gB_b for every timestep ------------
__global__ void __launch_bounds__(256) k_uB(const float* __restrict__ gBw,
                                            const float* __restrict__ gBb) {
    int t = blockIdx.x / NB;
    int b = blockIdx.x - t * NB;
    __shared__ float sWt[DI * 65];              // sWt[d*65+e] = W[e][d]
    __shared__ float su [VV * DI];
    __shared__ float sh [VV * DI];
    __shared__ float sM [VV * VV];
    int tid = threadIdx.x;

    for (int idx = tid; idx < DI * DI; idx += 256) {
        int d = idx & 63, e2 = idx >> 6;        // idx = e2*64+d
        sWt[d * 65 + e2] = gBw[idx];
    }
    for (int idx = tid; idx < VV * DI; idx += 256)
        su[idx] = g_u[(t * NN + b * VV) * DI + idx];
    for (int idx = tid; idx < VV * VV; idx += 256)
        sM[idx] = g_M[(b * VV) * VV + idx];
    __syncthreads();

    for (int task = tid; task < VV * DI; task += 256) {
        int i = task >> 6, e = task & 63;
        float acc = 0.f;
#pragma unroll 8
        for (int d = 0; d < DI; d++) acc += su[i * DI + d] * sWt[d * 65 + e];
        sh[task] = acc;
    }
    __syncthreads();

    for (int task = tid; task < VV * DI; task += 256) {
        int vv = task >> 6, e = task & 63;
        float acc = gBb[e];
#pragma unroll
        for (int i = 0; i < VV; i++) acc += sM[vv * VV + i] * sh[i * DI + e];
        g_uB[(t * NN + b * VV + vv) * DI + e] = acc;
    }
}

// ---------------- persistent scan: one CTA per (n-group, batch) --------------
// smem floats: WtA 4096 | WtC 4096 | Acol 256 | state 19*65*4 | H 19*64*4
//              | M 361 | bA 64 | bC 64  = 18741 floats
#define SCAN_SMEM_BYTES (18744 * 4)

__global__ void __launch_bounds__(608, 1) k_scan(
    const float* __restrict__ gAw, const float* __restrict__ gAb,
    const float* __restrict__ gCw, const float* __restrict__ gCb,
    const float* __restrict__ A_log) {
    extern __shared__ float smem[];
    float* sWtA   = smem;                       // [d*64+e] = WA[e][d]
    float* sWtC   = sWtA + 4096;
    float* sAcol  = sWtC + 4096;                // [e*4+j] = -exp(A_log[e][gi*4+j])
    float* sState = sAcol + 256;                // float4 per (vv,d), row stride 65
    float* sH     = sState + 4940;              // float4 per (i,e)
    float* sM     = sH + 4864;
    float* sbA    = sM + 361;
    float* sbC    = sbA + 64;

    int gi  = blockIdx.x;
    int b   = blockIdx.y;
    int tid = threadIdx.x;                      // 608 = 19 warps

    for (int idx = tid; idx < 4096; idx += 608) {
        int d = idx >> 6, e = idx & 63;
        sWtA[idx] = gAw[e * DI + d];
        sWtC[idx] = gCw[e * DI + d];
    }
    for (int idx = tid; idx < VV * VV; idx += 608) sM[idx] = g_M[(b * VV) * VV + idx];
    if (tid < 64) { sbA[tid] = gAb[tid]; sbC[tid] = gCb[tid]; }
    for (int idx = tid; idx < 256; idx += 608) {
        int e = idx >> 2, j = idx & 3;
        sAcol[idx] = -expf(A_log[e * DSTATE + gi * GS + j]);
    }
    for (int idx = tid; idx < 4940; idx += 608) sState[idx] = 0.f;
    __syncthreads();

    float4* sS4 = (float4*)sState;
    float4* sH4 = (float4*)sH;
    float4* sA4 = (float4*)sAcol;
    const int iv = tid >> 5;                    // vertex 0..18
    const int eb = tid & 31;                    // lane: handles e=eb and e=eb+32

    for (int t = 0; t < LSEQ; t++) {
        int nbase = t * NN + b * VV;

        // phase 1: hA[i][e][n] = sum_d WA[e][d] * s[i][d][n]
        {
            float4 a0 = make_float4(0,0,0,0), a1 = make_float4(0,0,0,0);
#pragma unroll 8
            for (int d = 0; d < DI; d++) {
                float4 s4 = sS4[iv * 65 + d];               // warp broadcast
                float w0 = sWtA[d * 64 + eb];
                float w1 = sWtA[d * 64 + eb + 32];
                a0.x += w0*s4.x; a0.y += w0*s4.y; a0.z += w0*s4.z; a0.w += w0*s4.w;
                a1.x += w1*s4.x; a1.y += w1*s4.y; a1.z += w1*s4.z; a1.w += w1*s4.w;
            }
            sH4[iv * 64 + eb]      = a0;
            sH4[iv * 64 + eb + 32] = a1;
        }
        __syncthreads();

        // phase 2: sA = M@hA + bA ; s_new = sA*exp(dt*A) + (uB*dt)*B
#pragma unroll
        for (int r = 0; r < 2; r++) {
            int task = tid + r * 608;                       // 1216 = 19*64
            int vv = task >> 6, e = task & 63;
            float ba = sbA[e];
            float4 acc = make_float4(ba, ba, ba, ba);
            const float* Mrow = sM + vv * VV;
#pragma unroll
            for (int i = 0; i < VV; i++) {
                float m = Mrow[i];
                float4 h = sH4[i * 64 + e];
                acc.x += m*h.x; acc.y += m*h.y; acc.z += m*h.z; acc.w += m*h.w;
            }
            int node = nbase + vv;
            float dtv = g_dt[node * DI + e];
            float ub  = g_uB[node * DI + e];
            float4 B4 = *(const float4*)&g_Bm[node * DSTATE + gi * GS];
            float4 A4 = sA4[e];
            float c = ub * dtv;
            float4 sn;
            sn.x = acc.x * __expf(dtv * A4.x) + c * B4.x;
            sn.y = acc.y * __expf(dtv * A4.y) + c * B4.y;
            sn.z = acc.z * __expf(dtv * A4.z) + c * B4.z;
            sn.w = acc.w * __expf(dtv * A4.w) + c * B4.w;
            sS4[vv * 65 + e] = sn;
        }
        __syncthreads();

        // phase 3: hC[i][e][n] = sum_d WC[e][d] * s_new[i][d][n]
        {
            float4 a0 = make_float4(0,0,0,0), a1 = make_float4(0,0,0,0);
#pragma unroll 8
            for (int d = 0; d < DI; d++) {
                float4 s4 = sS4[iv * 65 + d];
                float w0 = sWtC[d * 64 + eb];
                float w1 = sWtC[d * 64 + eb + 32];
                a0.x += w0*s4.x; a0.y += w0*s4.y; a0.z += w0*s4.z; a0.w += w0*s4.w;
                a1.x += w1*s4.x; a1.y += w1*s4.y; a1.z += w1*s4.z; a1.w += w1*s4.w;
            }
            sH4[iv * 64 + eb]      = a0;
            sH4[iv * 64 + eb + 32] = a1;
        }
        __syncthreads();

        // phase 4: sC = M@hC + bC ; y_partial = sum_n sC*C
#pragma unroll
        for (int r = 0; r < 2; r++) {
            int task = tid + r * 608;
            int vv = task >> 6, e = task & 63;
            float bc = sbC[e];
            float4 acc = make_float4(bc, bc, bc, bc);
            const float* Mrow = sM + vv * VV;
#pragma unroll
            for (int i = 0; i < VV; i++) {
                float m = Mrow[i];
                float4 h = sH4[i * 64 + e];
                acc.x += m*h.x; acc.y += m*h.y; acc.z += m*h.z; acc.w += m*h.w;
            }
            int node = nbase + vv;
            float4 C4 = *(const float4*)&g_Cm[node * DSTATE + gi * GS];
            g_yp[((node) * DI + e) * NG + gi] =
                acc.x*C4.x + acc.y*C4.y + acc.z*C4.z + acc.w*C4.w;
        }
        __syncthreads();
    }
}

// ---------------- epilogue: y = (sum_g yp + D*u) * silu(z); out = y @ Wout^T -
__global__ void __launch_bounds__(256) k_out(const float* __restrict__ Dp,
                                             const float* __restrict__ opw,
                                             float* __restrict__ out) {
    int v = blockIdx.x, t0 = blockIdx.y * 16;
    int tid = threadIdx.x;
    __shared__ __align__(16) float sy [16 * DI];
    __shared__ __align__(16) float sow[DM * DI];
    for (int idx = tid; idx < DM * DI; idx += 256) sow[idx] = opw[idx];
    const float4* yp4 = (const float4*)g_yp;
    for (int task = tid; task < 16 * DI; task += 256) {
        int p = task >> 6, e = task & 63;
        int idx = ((t0 + p) * NN + v) * DI + e;
        float4 a = yp4[idx];
        sy[task] = (a.x + a.y + a.z + a.w + Dp[e] * g_u[idx]) * g_sz[idx];
    }
    __syncthreads();
    for (int task = tid; task < 16 * DM; task += 256) {
        int p = task >> 5, m = task & 31;
        const float4* yr = (const float4*)(sy + p * DI);
        const float4* wr = (const float4*)(sow + m * DI);
        float acc = 0.f;
#pragma unroll
        for (int q = 0; q < 16; q++) {
            float4 a = yr[q], w = wr[q];
            acc += a.x*w.x + a.y*w.y + a.z*w.z + a.w*w.w;
        }
        out[(v * LSEQ + t0 + p) * DM + m] = acc;
    }
}

// ---------------- launch -----------------------------------------------------
extern "C" void kernel_launch(void* const* d_in, const int* in_sizes, int n_in,
                              void* d_out, int out_size) {
    const float* x_in  = (const float*)d_in[0];
    const int*   ei    = (const int*)  d_in[1];
    const float* ew    = (const float*)d_in[2];
    const float* ipw   = (const float*)d_in[3];
    const float* xpw   = (const float*)d_in[4];
    const float* dtw   = (const float*)d_in[5];
    const float* dtb   = (const float*)d_in[6];
    const float* A_log = (const float*)d_in[7];
    const float* Dp    = (const float*)d_in[8];
    const float* opw   = (const float*)d_in[9];
    const float* gAw   = (const float*)d_in[10];
    const float* gAb   = (const float*)d_in[11];
    const float* gBw   = (const float*)d_in[12];
    const float* gBb   = (const float*)d_in[13];
    const float* gCw   = (const float*)d_in[14];
    const float* gCb   = (const float*)d_in[15];
    float* out = (float*)d_out;
    int E = in_sizes[2];

    k_deg<<<NN, 256>>>(ei, ew, E);
    k_buildM<<<(E + NN + 255) / 256, 256>>>(ei, ew, E);
    k_proj<<<dim3(NN, LSEQ / 16), 128>>>(x_in, ipw, xpw, dtw, dtb);
    k_uB<<<LSEQ * NB, 256>>>(gBw, gBb);
    cudaFuncSetAttribute(k_scan, cudaFuncAttributeMaxDynamicSharedMemorySize,
                         SCAN_SMEM_BYTES);
    k_scan<<<dim3(NG, NB), 608, SCAN_SMEM_BYTES>>>(gAw, gAb, gCw, gCb, A_log);
    k_out<<<dim3(NN, LSEQ / 16), 256>>>(Dp, opw, out);
}

// round 7
// speedup vs baseline: 1.0724x; 1.0724x over previous
#include <cuda_runtime.h>
#include <math.h>

#define LSEQ   256
#define NN     608
#define DM     32
#define DI     64
#define DSTATE 16
#define NB     32
#define VV     19
#define NG     4
#define GS     4
#define PLANE  (LSEQ * NN * DI)

typedef unsigned long long ull;

// ---------------- packed fp32x2 helpers (sm_103a FFMA2 path) -----------------
__device__ __forceinline__ ull pack2(float x, float y) {
    ull r; asm("mov.b64 %0,{%1,%2};" : "=l"(r) : "f"(x), "f"(y)); return r;
}
__device__ __forceinline__ ull pack1(float x) {
    ull r; asm("mov.b64 %0,{%1,%1};" : "=l"(r) : "f"(x)); return r;
}
__device__ __forceinline__ void fma2(ull& d, ull a, ull b) {
    asm("fma.rn.f32x2 %0,%1,%2,%0;" : "+l"(d) : "l"(a), "l"(b));
}

// ---------------- scratch (__device__ globals; no runtime allocs) ------------
__device__ float g_deg[NN];
__device__ float g_M[NN * VV];                  // row v (=dst): M[v][src_local]
__device__ float g_u [LSEQ * NN * DI];
__device__ float g_dt[LSEQ * NN * DI];
__device__ float g_sz[LSEQ * NN * DI];
__device__ float g_uB[LSEQ * NN * DI];
__device__ float g_Bm[LSEQ * NN * DSTATE];
__device__ float g_Cm[LSEQ * NN * DSTATE];
__device__ float g_yp[NG * PLANE];              // [gi][t*NN+node][e]

// ---------------- degree (deterministic fixed-order reduction) ---------------
__global__ void k_deg(const int* __restrict__ ei, const float* __restrict__ ew, int E) {
    int v = blockIdx.x;
    if (threadIdx.x < VV) g_M[v * VV + threadIdx.x] = 0.f;
    float acc = 0.f;
    for (int e = threadIdx.x; e < E; e += 256)
        if (ei[E + e] == v) acc += ew[e];
    __shared__ float red[256];
    red[threadIdx.x] = acc;
    __syncthreads();
    for (int s = 128; s > 0; s >>= 1) {
        if (threadIdx.x < s) red[threadIdx.x] += red[threadIdx.x + s];
        __syncthreads();
    }
    if (threadIdx.x == 0) g_deg[v] = red[0] + 1.0f;
}

// ---------------- dense per-batch GCN norm matrix ---------------------------
__global__ void k_buildM(const int* __restrict__ ei, const float* __restrict__ ew, int E) {
    int i = blockIdx.x * 256 + threadIdx.x;
    if (i < E) {
        int s = ei[i], d = ei[E + i];
        int b = d / VV;
        int sl = s - b * VV;
        float ds = rsqrtf(fmaxf(g_deg[s], 1e-12f));
        float dd = rsqrtf(fmaxf(g_deg[d], 1e-12f));
        g_M[d * VV + sl] = ew[i] * ds * dd;
    } else if (i < E + NN) {
        int v = i - E;
        int vl = v % VV;
        float di = rsqrtf(fmaxf(g_deg[v], 1e-12f));
        g_M[v * VV + vl] = di * di;
    }
}

// ---------------- projections: u, silu(z), dt, B, C -------------------------
__global__ void __launch_bounds__(128) k_proj(
    const float* __restrict__ x_in, const float* __restrict__ ipw,
    const float* __restrict__ xpw,  const float* __restrict__ dtw,
    const float* __restrict__ dtb) {
    int v  = blockIdx.x;
    int t0 = blockIdx.y * 16;
    int e  = threadIdx.x;
    __shared__ __align__(16) float sxin[16 * DM];
    __shared__ __align__(16) float sx  [16 * DI];
    __shared__ float sdtr[16 * 2];

    for (int idx = e; idx < 16 * DM; idx += 128)
        sxin[idx] = x_in[(v * LSEQ + t0) * DM + idx];

    float4 w[8];
    const float4* ipw4 = (const float4*)ipw;
#pragma unroll
    for (int j = 0; j < 8; j++) w[j] = ipw4[e * 8 + j];
    __syncthreads();

#pragma unroll 4
    for (int p = 0; p < 16; p++) {
        const float4* xx = (const float4*)(sxin + p * DM);
        float acc = 0.f;
#pragma unroll
        for (int j = 0; j < 8; j++) {
            float4 a = xx[j];
            acc += w[j].x * a.x + w[j].y * a.y + w[j].z * a.z + w[j].w * a.w;
        }
        int base = ((t0 + p) * NN + v) * DI;
        if (e < DI) { sx[p * DI + e] = acc; g_u[base + e] = acc; }
        else        { g_sz[base + (e - DI)] = acc / (1.f + __expf(-acc)); }
    }
    __syncthreads();

    for (int task = e; task < 16 * 34; task += 128) {
        int p = task / 34, j = task - p * 34;
        const float4* xr = (const float4*)(sx + p * DI);
        const float4* wr = (const float4*)(xpw + j * DI);
        float acc = 0.f;
#pragma unroll
        for (int q = 0; q < 16; q++) {
            float4 a = xr[q], b = wr[q];
            acc += a.x * b.x + a.y * b.y + a.z * b.z + a.w * b.w;
        }
        int t = t0 + p;
        if (j < 2)       sdtr[p * 2 + j] = acc;
        else if (j < 18) g_Bm[(t * NN + v) * DSTATE + (j - 2)]  = acc;
        else             g_Cm[(t * NN + v) * DSTATE + (j - 18)] = acc;
    }
    __syncthreads();

    for (int task = e; task < 16 * 64; task += 128) {
        int p = task >> 6, d = task & 63;
        float xv = dtw[d * 2] * sdtr[p * 2] + dtw[d * 2 + 1] * sdtr[p * 2 + 1] + dtb[d];
        g_dt[((t0 + p) * NN + v) * DI + d] = (xv > 20.f) ? xv : log1pf(expf(xv));
    }
}

// ---------------- uB = M @ (u @ gB_w^T) + gB_b for every timestep ------------
__global__ void __launch_bounds__(256) k_uB(const float* __restrict__ gBw,
                                            const float* __restrict__ gBb) {
    int t = blockIdx.x / NB;
    int b = blockIdx.x - t * NB;
    __shared__ float sWt[DI * 65];
    __shared__ float su [VV * DI];
    __shared__ float sh [VV * DI];
    __shared__ float sM [VV * VV];
    int tid = threadIdx.x;

    for (int idx = tid; idx < DI * DI; idx += 256) {
        int d = idx & 63, e2 = idx >> 6;
        sWt[d * 65 + e2] = gBw[idx];
    }
    for (int idx = tid; idx < VV * DI; idx += 256)
        su[idx] = g_u[(t * NN + b * VV) * DI + idx];
    for (int idx = tid; idx < VV * VV; idx += 256)
        sM[idx] = g_M[(b * VV) * VV + idx];
    __syncthreads();

    for (int task = tid; task < VV * DI; task += 256) {
        int i = task >> 6, e = task & 63;
        float acc = 0.f;
#pragma unroll 8
        for (int d = 0; d < DI; d++) acc += su[i * DI + d] * sWt[d * 65 + e];
        sh[task] = acc;
    }
    __syncthreads();

    for (int task = tid; task < VV * DI; task += 256) {
        int vv = task >> 6, e = task & 63;
        float acc = gBb[e];
#pragma unroll
        for (int i = 0; i < VV; i++) acc += sM[vv * VV + i] * sh[i * DI + e];
        g_uB[(t * NN + b * VV + vv) * DI + e] = acc;
    }
}

// ---------------- persistent scan: one CTA per (n-group, batch) --------------
// smem floats: WtA 4096 | WtC 4096 | A 256 | state 19*260 | H 19*256
//              | M 361 | bA 64 | bC 64  = 18741 floats
#define SCAN_SMEM_BYTES (18744 * 4)

__global__ void __launch_bounds__(608, 1) k_scan(
    const float* __restrict__ gAw, const float* __restrict__ gAb,
    const float* __restrict__ gCw, const float* __restrict__ gCb,
    const float* __restrict__ A_log) {
    extern __shared__ float smem[];
    float* sWtA = smem;                 // [d*64+e] = WA[e][d]
    float* sWtC = sWtA + 4096;
    float* sAe  = sWtC + 4096;          // [e*4+n]
    float* sSt  = sAe + 256;            // [vv*260 + e*4 + n], float4 stride 65
    float* sH   = sSt + 4940;           // [i*256 + e*4 + n]
    float* sM   = sH + 4864;
    float* sbA  = sM + 361;
    float* sbC  = sbA + 64;

    int gi  = blockIdx.x;
    int b   = blockIdx.y;
    int tid = threadIdx.x;              // 608 = 19 warps

    for (int idx = tid; idx < 4096; idx += 608) {
        int d = idx >> 6, e = idx & 63;
        sWtA[idx] = gAw[e * DI + d];
        sWtC[idx] = gCw[e * DI + d];
    }
    for (int idx = tid; idx < VV * VV; idx += 608) sM[idx] = g_M[(b * VV) * VV + idx];
    if (tid < 64) { sbA[tid] = gAb[tid]; sbC[tid] = gCb[tid]; }
    for (int idx = tid; idx < 256; idx += 608) {
        int e = idx >> 2, j = idx & 3;
        sAe[idx] = -expf(A_log[e * DSTATE + gi * GS + j]);
    }
    for (int idx = tid; idx < 4940; idx += 608) sSt[idx] = 0.f;
    __syncthreads();

    const float4* sSt4 = (const float4*)sSt;
    ull* sH2 = (ull*)sH;

    const int iv = tid >> 5;            // vertex for phases 1/3
    const int eb = tid & 31;            // e lane: e=eb and e=eb+32

    // phases 2/4 mapping: 512 active threads = 2 groups x 256 (e,n) columns
    const bool act = tid < 512;
    const int c   = tid & 255;          // e*4+n
    const int gg  = tid >> 8;           // 0 or 1
    const int e2  = c >> 2, n2 = c & 3;
    const int vv0 = gg * 10;
    const int nvv = gg ? 9 : 10;
    const float Ae = act ? sAe[c] : 0.f;

    for (int t = 0; t < LSEQ; t++) {
        int nbase = t * NN + b * VV;

        // hoisted global loads for phases 2/4 (latency hidden under phase 1)
        float dtv[10], ubv[10], Bv[10], Cv[10];
        if (act) {
#pragma unroll
            for (int k = 0; k < 10; k++) {
                if (k < nvv) {
                    int node = nbase + vv0 + k;
                    dtv[k] = g_dt[node * DI + e2];
                    ubv[k] = g_uB[node * DI + e2];
                    Bv[k]  = g_Bm[node * DSTATE + gi * GS + n2];
                    Cv[k]  = g_Cm[node * DSTATE + gi * GS + n2];
                }
            }
        }

        // phase 1: hA[iv][e][n] = sum_d WA[e][d] * s[iv][d][n]   (fp32x2)
        {
            ull a0l = 0, a0h = 0, a1l = 0, a1h = 0;
#pragma unroll 16
            for (int d = 0; d < DI; d++) {
                float4 s = sSt4[iv * 65 + d];            // warp broadcast
                ull slo = pack2(s.x, s.y), shi = pack2(s.z, s.w);
                ull w0 = pack1(sWtA[d * 64 + eb]);
                ull w1 = pack1(sWtA[d * 64 + eb + 32]);
                fma2(a0l, w0, slo); fma2(a0h, w0, shi);
                fma2(a1l, w1, slo); fma2(a1h, w1, shi);
            }
            sH2[iv * 128 + eb * 2]            = a0l;
            sH2[iv * 128 + eb * 2 + 1]        = a0h;
            sH2[iv * 128 + (eb + 32) * 2]     = a1l;
            sH2[iv * 128 + (eb + 32) * 2 + 1] = a1h;
        }
        __syncthreads();

        // phase 2: sA = M@hA + bA ; s_new = sA*exp(dt*A) + (uB*dt)*B
        if (act) {
            float Hc[VV];
#pragma unroll
            for (int i = 0; i < VV; i++) Hc[i] = sH[i * 256 + c];
            float ba = sbA[e2];
#pragma unroll
            for (int k = 0; k < 10; k++) {
                if (k < nvv) {
                    int vv = vv0 + k;
                    float acc = ba;
                    const float* Mr = sM + vv * VV;
#pragma unroll
                    for (int i = 0; i < VV; i++) acc = fmaf(Mr[i], Hc[i], acc);
                    float ex = __expf(dtv[k] * Ae);
                    sSt[vv * 260 + c] = acc * ex + ubv[k] * dtv[k] * Bv[k];
                }
            }
        }
        __syncthreads();

        // phase 3: hC from the new state (fp32x2)
        {
            ull a0l = 0, a0h = 0, a1l = 0, a1h = 0;
#pragma unroll 16
            for (int d = 0; d < DI; d++) {
                float4 s = sSt4[iv * 65 + d];
                ull slo = pack2(s.x, s.y), shi = pack2(s.z, s.w);
                ull w0 = pack1(sWtC[d * 64 + eb]);
                ull w1 = pack1(sWtC[d * 64 + eb + 32]);
                fma2(a0l, w0, slo); fma2(a0h, w0, shi);
                fma2(a1l, w1, slo); fma2(a1h, w1, shi);
            }
            sH2[iv * 128 + eb * 2]            = a0l;
            sH2[iv * 128 + eb * 2 + 1]        = a0h;
            sH2[iv * 128 + (eb + 32) * 2]     = a1l;
            sH2[iv * 128 + (eb + 32) * 2 + 1] = a1h;
        }
        __syncthreads();

        // phase 4: sC = M@hC + bC ; y_part[vv][e] = sum_n sC*C (shuffle-reduce)
        if (act) {
            float Hc[VV];
#pragma unroll
            for (int i = 0; i < VV; i++) Hc[i] = sH[i * 256 + c];
            float bc = sbC[e2];
#pragma unroll
            for (int k = 0; k < 10; k++) {
                if (k < nvv) {
                    int vv = vv0 + k;
                    float acc = bc;
                    const float* Mr = sM + vv * VV;
#pragma unroll
                    for (int i = 0; i < VV; i++) acc = fmaf(Mr[i], Hc[i], acc);
                    float yv = acc * Cv[k];
                    yv += __shfl_xor_sync(0xffffffffu, yv, 1);
                    yv += __shfl_xor_sync(0xffffffffu, yv, 2);
                    if (n2 == 0) {
                        int node = nbase + vv;
                        g_yp[gi * PLANE + node * DI + e2] = yv;
                    }
                }
            }
        }
        __syncthreads();
    }
}

// ---------------- epilogue: y = (sum_g yp + D*u) * silu(z); out = y @ Wout^T -
__global__ void __launch_bounds__(256) k_out(const float* __restrict__ Dp,
                                             const float* __restrict__ opw,
                                             float* __restrict__ out) {
    int v = blockIdx.x, t0 = blockIdx.y * 16;
    int tid = threadIdx.x;
    __shared__ __align__(16) float sy [16 * DI];
    __shared__ __align__(16) float sow[DM * DI];
    for (int idx = tid; idx < DM * DI; idx += 256) sow[idx] = opw[idx];
    for (int task = tid; task < 16 * DI; task += 256) {
        int p = task >> 6, e = task & 63;
        int idx = ((t0 + p) * NN + v) * DI + e;
        float a = g_yp[idx] + g_yp[PLANE + idx] + g_yp[2 * PLANE + idx]
                + g_yp[3 * PLANE + idx];
        sy[task] = (a + Dp[e] * g_u[idx]) * g_sz[idx];
    }
    __syncthreads();
    for (int task = tid; task < 16 * DM; task += 256) {
        int p = task >> 5, m = task & 31;
        const float4* yr = (const float4*)(sy + p * DI);
        const float4* wr = (const float4*)(sow + m * DI);
        float acc = 0.f;
#pragma unroll
        for (int q = 0; q < 16; q++) {
            float4 a = yr[q], w = wr[q];
            acc += a.x * w.x + a.y * w.y + a.z * w.z + a.w * w.w;
        }
        out[(v * LSEQ + t0 + p) * DM + m] = acc;
    }
}

// ---------------- launch -----------------------------------------------------
extern "C" void kernel_launch(void* const* d_in, const int* in_sizes, int n_in,
                              void* d_out, int out_size) {
    const float* x_in  = (const float*)d_in[0];
    const int*   ei    = (const int*)  d_in[1];
    const float* ew    = (const float*)d_in[2];
    const float* ipw   = (const float*)d_in[3];
    const float* xpw   = (const float*)d_in[4];
    const float* dtw   = (const float*)d_in[5];
    const float* dtb   = (const float*)d_in[6];
    const float* A_log = (const float*)d_in[7];
    const float* Dp    = (const float*)d_in[8];
    const float* opw   = (const float*)d_in[9];
    const float* gAw   = (const float*)d_in[10];
    const float* gAb   = (const float*)d_in[11];
    const float* gBw   = (const float*)d_in[12];
    const float* gBb   = (const float*)d_in[13];
    const float* gCw   = (const float*)d_in[14];
    const float* gCb   = (const float*)d_in[15];
    float* out = (float*)d_out;
    int E = in_sizes[2];

    k_deg<<<NN, 256>>>(ei, ew, E);
    k_buildM<<<(E + NN + 255) / 256, 256>>>(ei, ew, E);
    k_proj<<<dim3(NN, LSEQ / 16), 128>>>(x_in, ipw, xpw, dtw, dtb);
    k_uB<<<LSEQ * NB, 256>>>(gBw, gBb);
    cudaFuncSetAttribute(k_scan, cudaFuncAttributeMaxDynamicSharedMemorySize,
                         SCAN_SMEM_BYTES);
    k_scan<<<dim3(NG, NB), 608, SCAN_SMEM_BYTES>>>(gAw, gAb, gCw, gCb, A_log);
    k_out<<<dim3(NN, LSEQ / 16), 256>>>(Dp, opw, out);
}

// round 8
// speedup vs baseline: 1.0862x; 1.0128x over previous
#include <cuda_runtime.h>
#include <math.h>

#define LSEQ   256
#define NN     608
#define DM     32
#define DI     64
#define DSTATE 16
#define NB     32
#define VV     19
#define NG     4
#define GS     4
#define PLANE  (LSEQ * NN * DI)

typedef unsigned long long ull;

// ---------------- packed fp32x2 helpers (sm_103a FFMA2 path) -----------------
__device__ __forceinline__ ull pack2(float x, float y) {
    ull r; asm("mov.b64 %0,{%1,%2};" : "=l"(r) : "f"(x), "f"(y)); return r;
}
__device__ __forceinline__ ull pack1(float x) {
    ull r; asm("mov.b64 %0,{%1,%1};" : "=l"(r) : "f"(x)); return r;
}
__device__ __forceinline__ void fma2(ull& d, ull a, ull b) {
    asm("fma.rn.f32x2 %0,%1,%2,%0;" : "+l"(d) : "l"(a), "l"(b));
}
__device__ __forceinline__ void unpk2(float& x, float& y, ull v) {
    asm("mov.b64 {%0,%1},%2;" : "=f"(x), "=f"(y) : "l"(v));
}

// ---------------- scratch (__device__ globals; no runtime allocs) ------------
__device__ float g_deg[NN];
__device__ float g_M[NN * VV];                  // row v (=dst): M[v][src_local]
__device__ float g_u [LSEQ * NN * DI];
__device__ float g_dt[LSEQ * NN * DI];
__device__ float g_sz[LSEQ * NN * DI];
__device__ float g_uB[LSEQ * NN * DI];
__device__ float g_Bm[LSEQ * NN * DSTATE];
__device__ float g_Cm[LSEQ * NN * DSTATE];
__device__ float g_yp[NG * PLANE];              // [gi][t*NN+node][e]

// ---------------- degree (deterministic fixed-order reduction) ---------------
__global__ void k_deg(const int* __restrict__ ei, const float* __restrict__ ew, int E) {
    int v = blockIdx.x;
    if (threadIdx.x < VV) g_M[v * VV + threadIdx.x] = 0.f;
    float acc = 0.f;
    for (int e = threadIdx.x; e < E; e += 256)
        if (ei[E + e] == v) acc += ew[e];
    __shared__ float red[256];
    red[threadIdx.x] = acc;
    __syncthreads();
    for (int s = 128; s > 0; s >>= 1) {
        if (threadIdx.x < s) red[threadIdx.x] += red[threadIdx.x + s];
        __syncthreads();
    }
    if (threadIdx.x == 0) g_deg[v] = red[0] + 1.0f;
}

// ---------------- dense per-batch GCN norm matrix ---------------------------
__global__ void k_buildM(const int* __restrict__ ei, const float* __restrict__ ew, int E) {
    int i = blockIdx.x * 256 + threadIdx.x;
    if (i < E) {
        int s = ei[i], d = ei[E + i];
        int b = d / VV;
        int sl = s - b * VV;
        float ds = rsqrtf(fmaxf(g_deg[s], 1e-12f));
        float dd = rsqrtf(fmaxf(g_deg[d], 1e-12f));
        g_M[d * VV + sl] = ew[i] * ds * dd;
    } else if (i < E + NN) {
        int v = i - E;
        int vl = v % VV;
        float di = rsqrtf(fmaxf(g_deg[v], 1e-12f));
        g_M[v * VV + vl] = di * di;
    }
}

// ---------------- fused prep: projections + uB precompute --------------------
// block = (batch b, 8-timestep chunk). 256 threads.
// smem floats: regionA 9728 (sxin 4864 then sh) | su 9728 | sxpw 2176
//              | sWt 4160 | sM 361 | sdtr 304 | sdtw 128 | sdtb 64 | sgBb 64
#define PREP_SMEM_FLOATS (9728 + 9728 + 2176 + 4160 + 361 + 304 + 128 + 64 + 64)
#define PREP_SMEM_BYTES  (PREP_SMEM_FLOATS * 4)

__global__ void __launch_bounds__(256) k_prep(
    const float* __restrict__ x_in, const float* __restrict__ ipw,
    const float* __restrict__ xpw,  const float* __restrict__ dtw,
    const float* __restrict__ dtb,  const float* __restrict__ gBw,
    const float* __restrict__ gBb) {
    extern __shared__ float sm[];
    float* regA = sm;                    // sxin first 4864, later sh (9728)
    float* su   = regA + 9728;
    float* sxpw = su + 9728;
    float* sWt  = sxpw + 2176;
    float* sM   = sWt + 4160;
    float* sdtr = sM + 361;
    float* sdtw = sdtr + 304;
    float* sdtb = sdtw + 128;
    float* sgBb = sdtb + 64;

    int b  = blockIdx.x;
    int t0 = blockIdx.y * 8;
    int tid = threadIdx.x;

    // loads
    for (int idx = tid; idx < 8 * VV * DM; idx += 256) {
        int t = idx / (VV * DM), r = idx - t * (VV * DM);
        int v = r / DM, m = r - v * DM;
        regA[idx] = x_in[((b * VV + v) * LSEQ + t0 + t) * DM + m];
    }
    for (int idx = tid; idx < 34 * DI; idx += 256) sxpw[idx] = xpw[idx];
    for (int idx = tid; idx < DI * DI; idx += 256) {
        int e = idx >> 6, d = idx & 63;
        sWt[d * 65 + e] = gBw[idx];
    }
    for (int idx = tid; idx < VV * VV; idx += 256) sM[idx] = g_M[(b * VV) * VV + idx];
    if (tid < 128) sdtw[tid] = dtw[tid];
    if (tid < 64)  { sdtb[tid] = dtb[tid]; sgBb[tid] = gBb[tid]; }

    int e_r = tid & 127;
    int th  = tid >> 7;
    float4 w8[8];
    const float4* ipw4 = (const float4*)ipw;
#pragma unroll
    for (int j = 0; j < 8; j++) w8[j] = ipw4[e_r * 8 + j];
    __syncthreads();

    // xz projection: u, silu(z)
    for (int tt = 0; tt < 4; tt++) {
        int t = th * 4 + tt;
#pragma unroll 1
        for (int v = 0; v < VV; v++) {
            const float4* xx = (const float4*)(regA + t * (VV * DM) + v * DM);
            float acc = 0.f;
#pragma unroll
            for (int j = 0; j < 8; j++) {
                float4 a = xx[j];
                acc += w8[j].x * a.x + w8[j].y * a.y + w8[j].z * a.z + w8[j].w * a.w;
            }
            int base = ((t0 + t) * NN + b * VV + v) * DI;
            if (e_r < DI) {
                su[t * (VV * DI) + v * DI + e_r] = acc;
                g_u[base + e_r] = acc;
            } else {
                g_sz[base + (e_r - DI)] = acc / (1.f + __expf(-acc));
            }
        }
    }
    __syncthreads();

    // x_dbl: dtr, B, C
    for (int task = tid; task < 8 * VV * 34; task += 256) {
        int j = task % 34, r = task / 34;
        int t = r / VV, v = r - t * VV;
        const float4* xr = (const float4*)(su + t * (VV * DI) + v * DI);
        const float4* wr = (const float4*)(sxpw + j * DI);
        float acc = 0.f;
#pragma unroll
        for (int q = 0; q < 16; q++) {
            float4 a = xr[q], w = wr[q];
            acc += a.x * w.x + a.y * w.y + a.z * w.z + a.w * w.w;
        }
        int node = (t0 + t) * NN + b * VV + v;
        if (j < 2)       sdtr[r * 2 + j] = acc;
        else if (j < 18) g_Bm[node * DSTATE + (j - 2)]  = acc;
        else             g_Cm[node * DSTATE + (j - 18)] = acc;
    }
    __syncthreads();

    // dt = softplus(dtr @ dtw^T + dtb)
    for (int task = tid; task < 8 * VV * DI; task += 256) {
        int d = task & 63, r = task >> 6;
        int t = r / VV, v = r - t * VV;
        float xv = sdtw[d * 2] * sdtr[r * 2] + sdtw[d * 2 + 1] * sdtr[r * 2 + 1] + sdtb[d];
        g_dt[((t0 + t) * NN + b * VV + v) * DI + d] = (xv > 20.f) ? xv : log1pf(expf(xv));
    }

    // h = u @ gBw^T  (regionA reused: sxin dead)
    for (int task = tid; task < 8 * VV * DI; task += 256) {
        int e = task & 63, r = task >> 6;
        int t = r / VV, v = r - t * VV;
        const float* ur = su + t * (VV * DI) + v * DI;
        float acc = 0.f;
#pragma unroll 8
        for (int d = 0; d < DI; d++) acc += ur[d] * sWt[d * 65 + e];
        regA[t * (VV * DI) + v * DI + e] = acc;
    }
    __syncthreads();

    // uB = M @ h + gBb
    for (int task = tid; task < 8 * VV * DI; task += 256) {
        int e = task & 63, r = task >> 6;
        int t = r / VV, v = r - t * VV;
        float acc = sgBb[e];
        const float* Mr = sM + v * VV;
        const float* hb = regA + t * (VV * DI) + e;
#pragma unroll
        for (int i = 0; i < VV; i++) acc += Mr[i] * hb[i * DI];
        g_uB[((t0 + t) * NN + b * VV + v) * DI + e] = acc;
    }
}

// ---------------- persistent scan: one CTA per (n-group, batch) --------------
// smem floats: WtA 4096 | WtC 4096 | Ae 256 | sSt 4940 | sH 4864
//              | sM2 722 (ull dup) | bA 64 | bC 64  = 19102
#define SCAN_SMEM_BYTES (19104 * 4)

__global__ void __launch_bounds__(608, 1) k_scan(
    const float* __restrict__ gAw, const float* __restrict__ gAb,
    const float* __restrict__ gCw, const float* __restrict__ gCb,
    const float* __restrict__ A_log) {
    extern __shared__ float smem[];
    float* sWtA = smem;                 // [d*64+e] = WA[e][d]
    float* sWtC = sWtA + 4096;
    float* sAe  = sWtC + 4096;          // [e*4+n]
    float* sSt  = sAe + 256;            // [vv*260 + d*4 + n]
    float* sH   = sSt + 4940;           // [i*256 + e*4 + n]
    ull*   sM2  = (ull*)(sH + 4864);    // 361 duplicated pairs
    float* sbA  = (float*)(sM2 + 361);
    float* sbC  = sbA + 64;

    int gi  = blockIdx.x;
    int b   = blockIdx.y;
    int tid = threadIdx.x;              // 608 = 19 warps

    for (int idx = tid; idx < 4096; idx += 608) {
        int d = idx >> 6, e = idx & 63;
        sWtA[idx] = gAw[e * DI + d];
        sWtC[idx] = gCw[e * DI + d];
    }
    for (int idx = tid; idx < VV * VV; idx += 608)
        sM2[idx] = pack1(g_M[(b * VV) * VV + idx]);
    if (tid < 64) { sbA[tid] = gAb[tid]; sbC[tid] = gCb[tid]; }
    for (int idx = tid; idx < 256; idx += 608) {
        int e = idx >> 2, j = idx & 3;
        sAe[idx] = -expf(A_log[e * DSTATE + gi * GS + j]);
    }
    for (int idx = tid; idx < 4940; idx += 608) sSt[idx] = 0.f;
    __syncthreads();

    const ulonglong2* sSt2 = (const ulonglong2*)sSt;  // idx (vv*65 + d)
    ull* sH2 = (ull*)sH;                              // idx (i*128 + e*2 + hf)

    const int iv = tid >> 5;            // vertex for phases 1/3
    const int eb = tid & 31;            // e lane: e=eb and e=eb+32

    // phases 2/4 mapping: 512 threads = 4 vv-groups x 64 e x 2 n-halves
    const bool act = tid < 512;
    const int c7  = tid & 127;          // = e2*2 + hf
    const int e2  = c7 >> 1, hf = c7 & 1;
    const int grp = (tid >> 7) & 3;
    const int vvs = grp * 5;
    const int nvv = (grp < 3) ? 5 : 4;
    float aE0 = 0.f, aE1 = 0.f, bAv = 0.f, bCv = 0.f;
    if (act) {
        aE0 = sAe[e2 * 4 + hf * 2];
        aE1 = sAe[e2 * 4 + hf * 2 + 1];
        bAv = sbA[e2]; bCv = sbC[e2];
    }

    for (int t = 0; t < LSEQ; t++) {
        int nbase = t * NN + b * VV;

        // hoisted global loads (latency hidden under phase 1)
        float dtv[5], ubv[5];
        float2 B2[5], C2[5];
        if (act) {
#pragma unroll
            for (int k = 0; k < 5; k++) {
                if (k < nvv) {
                    int node = nbase + vvs + k;
                    dtv[k] = g_dt[node * DI + e2];
                    ubv[k] = g_uB[node * DI + e2];
                    B2[k]  = *(const float2*)&g_Bm[node * DSTATE + gi * GS + hf * 2];
                    C2[k]  = *(const float2*)&g_Cm[node * DSTATE + gi * GS + hf * 2];
                }
            }
        }

        // phase 1: hA[iv][e][n] = sum_d WA[e][d] * s[iv][d][n]   (mov-free f32x2)
        {
            ull a0l = 0, a0h = 0, a1l = 0, a1h = 0;
#pragma unroll 16
            for (int d = 0; d < DI; d++) {
                ulonglong2 s2 = sSt2[iv * 65 + d];       // warp broadcast
                ull w0 = pack1(sWtA[d * 64 + eb]);
                ull w1 = pack1(sWtA[d * 64 + eb + 32]);
                fma2(a0l, w0, s2.x); fma2(a0h, w0, s2.y);
                fma2(a1l, w1, s2.x); fma2(a1h, w1, s2.y);
            }
            sH2[iv * 128 + eb * 2]            = a0l;
            sH2[iv * 128 + eb * 2 + 1]        = a0h;
            sH2[iv * 128 + (eb + 32) * 2]     = a1l;
            sH2[iv * 128 + (eb + 32) * 2 + 1] = a1h;
        }
        __syncthreads();

        // phase 2: sA = M@hA + bA ; s_new = sA*exp(dt*A) + (uB*dt)*B
        if (act) {
            ull Hc[VV];
#pragma unroll
            for (int i = 0; i < VV; i++) Hc[i] = sH2[i * 128 + c7];
#pragma unroll
            for (int k = 0; k < 5; k++) {
                if (k < nvv) {
                    int vv = vvs + k;
                    ull acc = pack2(bAv, bAv);
                    const ull* M2r = sM2 + vv * VV;
#pragma unroll
                    for (int i = 0; i < VV; i++) fma2(acc, M2r[i], Hc[i]);
                    float a0, a1; unpk2(a0, a1, acc);
                    float dv = dtv[k], cb = ubv[k] * dv;
                    float s0 = a0 * __expf(dv * aE0) + cb * B2[k].x;
                    float s1 = a1 * __expf(dv * aE1) + cb * B2[k].y;
                    *(float2*)&sSt[vv * 260 + e2 * 4 + hf * 2] = make_float2(s0, s1);
                }
            }
        }
        __syncthreads();

        // phase 3: hC from the new state
        {
            ull a0l = 0, a0h = 0, a1l = 0, a1h = 0;
#pragma unroll 16
            for (int d = 0; d < DI; d++) {
                ulonglong2 s2 = sSt2[iv * 65 + d];
                ull w0 = pack1(sWtC[d * 64 + eb]);
                ull w1 = pack1(sWtC[d * 64 + eb + 32]);
                fma2(a0l, w0, s2.x); fma2(a0h, w0, s2.y);
                fma2(a1l, w1, s2.x); fma2(a1h, w1, s2.y);
            }
            sH2[iv * 128 + eb * 2]            = a0l;
            sH2[iv * 128 + eb * 2 + 1]        = a0h;
            sH2[iv * 128 + (eb + 32) * 2]     = a1l;
            sH2[iv * 128 + (eb + 32) * 2 + 1] = a1h;
        }
        __syncthreads();

        // phase 4: sC = M@hC + bC ; y_part = sum_n sC*C (pair + 1 shfl)
        if (act) {
            ull Hc[VV];
#pragma unroll
            for (int i = 0; i < VV; i++) Hc[i] = sH2[i * 128 + c7];
#pragma unroll
            for (int k = 0; k < 5; k++) {
                if (k < nvv) {
                    int vv = vvs + k;
                    ull acc = pack2(bCv, bCv);
                    const ull* M2r = sM2 + vv * VV;
#pragma unroll
                    for (int i = 0; i < VV; i++) fma2(acc, M2r[i], Hc[i]);
                    float a0, a1; unpk2(a0, a1, acc);
                    float yv = a0 * C2[k].x + a1 * C2[k].y;
                    yv += __shfl_xor_sync(0xffffffffu, yv, 1);
                    if (hf == 0)
                        g_yp[gi * PLANE + (nbase + vv) * DI + e2] = yv;
                }
            }
        }
        __syncthreads();
    }
}

// ---------------- epilogue: y = (sum_g yp + D*u) * silu(z); out = y @ Wout^T -
__global__ void __launch_bounds__(256) k_out(const float* __restrict__ Dp,
                                             const float* __restrict__ opw,
                                             float* __restrict__ out) {
    int v = blockIdx.x, t0 = blockIdx.y * 16;
    int tid = threadIdx.x;
    __shared__ __align__(16) float sy [16 * DI];
    __shared__ __align__(16) float sow[DM * DI];
    for (int idx = tid; idx < DM * DI; idx += 256) sow[idx] = opw[idx];
    for (int task = tid; task < 16 * DI; task += 256) {
        int p = task >> 6, e = task & 63;
        int idx = ((t0 + p) * NN + v) * DI + e;
        float a = g_yp[idx] + g_yp[PLANE + idx] + g_yp[2 * PLANE + idx]
                + g_yp[3 * PLANE + idx];
        sy[task] = (a + Dp[e] * g_u[idx]) * g_sz[idx];
    }
    __syncthreads();
    for (int task = tid; task < 16 * DM; task += 256) {
        int p = task >> 5, m = task & 31;
        const float4* yr = (const float4*)(sy + p * DI);
        const float4* wr = (const float4*)(sow + m * DI);
        float acc = 0.f;
#pragma unroll
        for (int q = 0; q < 16; q++) {
            float4 a = yr[q], w = wr[q];
            acc += a.x * w.x + a.y * w.y + a.z * w.z + a.w * w.w;
        }
        out[(v * LSEQ + t0 + p) * DM + m] = acc;
    }
}

// ---------------- launch -----------------------------------------------------
extern "C" void kernel_launch(void* const* d_in, const int* in_sizes, int n_in,
                              void* d_out, int out_size) {
    const float* x_in  = (const float*)d_in[0];
    const int*   ei    = (const int*)  d_in[1];
    const float* ew    = (const float*)d_in[2];
    const float* ipw   = (const float*)d_in[3];
    const float* xpw   = (const float*)d_in[4];
    const float* dtw   = (const float*)d_in[5];
    const float* dtb   = (const float*)d_in[6];
    const float* A_log = (const float*)d_in[7];
    const float* Dp    = (const float*)d_in[8];
    const float* opw   = (const float*)d_in[9];
    const float* gAw   = (const float*)d_in[10];
    const float* gAb   = (const float*)d_in[11];
    const float* gBw   = (const float*)d_in[12];
    const float* gBb   = (const float*)d_in[13];
    const float* gCw   = (const float*)d_in[14];
    const float* gCb   = (const float*)d_in[15];
    float* out = (float*)d_out;
    int E = in_sizes[2];

    k_deg<<<NN, 256>>>(ei, ew, E);
    k_buildM<<<(E + NN + 255) / 256, 256>>>(ei, ew, E);
    cudaFuncSetAttribute(k_prep, cudaFuncAttributeMaxDynamicSharedMemorySize,
                         PREP_SMEM_BYTES);
    k_prep<<<dim3(NB, LSEQ / 8), 256, PREP_SMEM_BYTES>>>(x_in, ipw, xpw, dtw,
                                                         dtb, gBw, gBb);
    cudaFuncSetAttribute(k_scan, cudaFuncAttributeMaxDynamicSharedMemorySize,
                         SCAN_SMEM_BYTES);
    k_scan<<<dim3(NG, NB), 608, SCAN_SMEM_BYTES>>>(gAw, gAb, gCw, gCb, A_log);
    k_out<<<dim3(NN, LSEQ / 16), 256>>>(Dp, opw, out);
}